// round 9
// baseline (speedup 1.0000x reference)
#include <cuda_runtime.h>
#include <cuda_bf16.h>

#define N   8192
#define B   4096                 // time buckets
#define CS  8                    // cluster size == grid size
#define T   256                  // threads per CTA
#define PT  4                    // elements per thread  (N / (CS*T))
#define BPB (B / CS)             // 512 buckets "owned" per CTA (cursors/reset)

__device__ __align__(16) int    g_cnt[B];    // zero-init; re-zeroed each run
__device__ __align__(16) float  g_bsum[B];   // zero-init; re-zeroed each run
__device__ int    g_cur[B];                  // rewritten each run
__device__ float2 g_ste[N];                  // bucket-sorted (t, e)
__device__ float  g_accum;                   // zero-init; reset by last CTA
__device__ int    g_done;                    // zero-init; reset by last CTA

#define CLUSTER_SYNC() do { \
    asm volatile("barrier.cluster.arrive.aligned;" ::: "memory"); \
    asm volatile("barrier.cluster.wait.aligned;"   ::: "memory"); } while (0)

// O(N) Cox loss on an 8-CTA cluster (HW barrier => deadlock-free):
// 1) per-CTA slice: exp + bucket-count/sum atomics (spreads MUFU over 8 SMs)
// 2) each CTA redundantly block-scans all 4096 buckets into LOCAL smem
// 3) counting-sort scatter via global atomic cursors
// 4) per-i: rs = S - prefix_incl(bucket) + exact in-bucket compare; log; loss
__global__ void __cluster_dims__(CS, 1, 1) __launch_bounds__(T, 1)
cox_cluster_kernel(const float* __restrict__ hazard,
                   const float* __restrict__ time,
                   const float* __restrict__ censor,
                   float* __restrict__ out)
{
    __shared__ int   off[B + 1];    // exclusive count prefix (off[B] = N)
    __shared__ float preI[B];       // inclusive exp-sum prefix
    __shared__ int   wti[8];
    __shared__ float wtf[8];
    __shared__ float red[T];

    const int tid  = threadIdx.x;
    const int lane = tid & 31;
    const int w    = tid >> 5;
    const int r    = blockIdx.x;    // cluster rank 0..7

    // ---- Phase 1: load slice, exp, bucket atomics ----
    float tv[PT], hv[PT], ev[PT];
#pragma unroll
    for (int k = 0; k < PT; ++k) {
        const int j = r * (T * PT) + k * T + tid;   // coalesced
        tv[k] = time[j];
        hv[k] = hazard[j];
        ev[k] = __expf(hv[k]);
        const int b = min((int)(tv[k] * (float)B), B - 1);
        atomicAdd(&g_cnt[b], 1);
        atomicAdd(&g_bsum[b], ev[k]);
    }
    __threadfence();
    CLUSTER_SYNC();

    // ---- Phase 2: full redundant scan of all B buckets into local smem ----
    int c[16]; float f[16];
    {
        const int4*   c4 = (const int4*)(&g_cnt[tid * 16]);
        const float4* f4 = (const float4*)(&g_bsum[tid * 16]);
#pragma unroll
        for (int q = 0; q < 4; ++q) {
            const int4   a  = c4[q];
            const float4 bb = f4[q];
            c[q*4+0]=a.x;  c[q*4+1]=a.y;  c[q*4+2]=a.z;  c[q*4+3]=a.w;
            f[q*4+0]=bb.x; f[q*4+1]=bb.y; f[q*4+2]=bb.z; f[q*4+3]=bb.w;
        }
    }
    int ci = 0; float fi = 0.0f;
#pragma unroll
    for (int q = 0; q < 16; ++q) { ci += c[q]; fi += f[q]; }

    int si = ci; float sf = fi;                      // warp inclusive scan
#pragma unroll
    for (int o = 1; o < 32; o <<= 1) {
        const int   ai = __shfl_up_sync(0xffffffffu, si, o);
        const float af = __shfl_up_sync(0xffffffffu, sf, o);
        if (lane >= o) { si += ai; sf += af; }
    }
    if (lane == 31) { wti[w] = si; wtf[w] = sf; }
    __syncthreads();
    if (w == 0 && lane < 8) {                        // scan 8 warp totals
        int vi = wti[lane]; float vf = wtf[lane];
#pragma unroll
        for (int o = 1; o < 8; o <<= 1) {
            const int   ai = __shfl_up_sync(0x000000ffu, vi, o);
            const float af = __shfl_up_sync(0x000000ffu, vf, o);
            if (lane >= o) { vi += ai; vf += af; }
        }
        wti[lane] = vi; wtf[lane] = vf;
    }
    __syncthreads();
    int   bi = (w ? wti[w - 1] : 0)    + (si - ci);  // exclusive thread base
    float bf = (w ? wtf[w - 1] : 0.0f) + (sf - fi);
#pragma unroll
    for (int q = 0; q < 16; ++q) {
        off[tid * 16 + q] = bi;
        bf += f[q];
        preI[tid * 16 + q] = bf;                     // inclusive
        bi += c[q];
    }
    if (tid == 0) off[B] = N;
    __syncthreads();
    const float S = wtf[7];                          // grand total of exp

    // cursor init for this CTA's owned bucket slice
#pragma unroll
    for (int q = 0; q < BPB / T; ++q) {              // 2 per thread
        const int b = r * BPB + q * T + tid;
        g_cur[b] = off[b];
    }
    __threadfence();
    CLUSTER_SYNC();

    // ---- Phase 3: counting-sort scatter of this slice ----
#pragma unroll
    for (int k = 0; k < PT; ++k) {
        const int b = min((int)(tv[k] * (float)B), B - 1);
        const int p = atomicAdd(&g_cur[b], 1);
        g_ste[p] = make_float2(tv[k], ev[k]);
    }
    __threadfence();
    CLUSTER_SYNC();

    // ---- Phase 4: per-i risk sum + loss ----
    float acc = 0.0f;
#pragma unroll
    for (int k = 0; k < PT; ++k) {
        const int   i  = r * (T * PT) + k * T + tid;
        const float ti = tv[k];
        const int   b  = min((int)(ti * (float)B), B - 1);
        float rs = S - preI[b];                      // buckets strictly above b
        const int p0 = off[b], p1 = off[b + 1];      // avg 2 mates
        for (int p = p0; p < p1; ++p) {
            const float2 m = g_ste[p];
            if (m.x >= ti) rs += m.y;                // exact in-bucket compare
        }
        acc += (hv[k] - __logf(rs)) * censor[i];
    }
    // re-zero bucket state for the next graph replay (no one reads it now)
#pragma unroll
    for (int q = 0; q < BPB / T; ++q) {
        const int b = r * BPB + q * T + tid;
        g_cnt[b]  = 0;
        g_bsum[b] = 0.0f;
    }

    // ---- Block reduce + last-CTA fold ----
    red[tid] = acc;
    __syncthreads();
    if (tid < 128) red[tid] += red[tid + 128];
    __syncthreads();
    if (tid < 64)  red[tid] += red[tid + 64];
    __syncthreads();
    if (tid < 32) {
        float v = red[tid] + red[tid + 32];
#pragma unroll
        for (int o = 16; o > 0; o >>= 1)
            v += __shfl_down_sync(0xffffffffu, v, o);
        if (tid == 0) {
            atomicAdd(&g_accum, v);
            __threadfence();
            if (atomicAdd(&g_done, 1) == CS - 1) {   // all partials are in
                const float tot = atomicAdd(&g_accum, 0.0f);
                out[0] = -tot / (float)N;
                g_accum = 0.0f;                      // reset for next replay
                g_done  = 0;
            }
        }
    }
}

extern "C" void kernel_launch(void* const* d_in, const int* in_sizes, int n_in,
                              void* d_out, int out_size)
{
    const float* hazard = (const float*)d_in[0];
    const float* time_  = (const float*)d_in[1];
    const float* censor = (const float*)d_in[2];
    float* out = (float*)d_out;

    cox_cluster_kernel<<<CS, T>>>(hazard, time_, censor, out);
}